// round 1
// baseline (speedup 1.0000x reference)
#include <cuda_runtime.h>
#include <math.h>

// ---------------- problem constants ----------------
#define Bsz   8
#define Tfull 1600
#define Dm    512
#define DIc   1024
#define Nst   16
#define Rr    32
#define Ll    8
#define Vv    1024
#define T4    400
#define M4    (Bsz*T4)    // 3200 rows after subsampling
#define M2    (Bsz*800)   // 6400 rows after conv1

// ---------------- scratch buffer (single __device__ array) ----------------
// featsp : 8*1602*80  = 1,025,280   @ 0
// w1t    : 240*512    = 122,880     @ 1,025,280
// w2t    : 1536*512   = 786,432     @ 1,148,160
// out1p  : 8*802*512  = 3,284,992   @ 1,934,592
// x      : 3200*512   = 1,638,400   @ 5,219,584
// xn     : 3200*512   = 1,638,400   @ 6,857,984
// xz     : 3200*2048  = 6,553,600   @ 8,496,384
// xi     : 3200*1024  = 3,276,800   @ 15,049,984
// dt     : 3200*1024  = 3,276,800   @ 18,326,784
// proj   : 3200*64    =   204,800   @ 21,603,584
// yc     : 3200*1024  = 3,276,800   @ 21,808,384
// total 25,085,184 floats (~100 MB)
__device__ float g_buf[25085184];

#define OFF_FEATSP 0
#define OFF_W1T    1025280
#define OFF_W2T    1148160
#define OFF_OUT1P  1934592
#define OFF_X      5219584
#define OFF_XN     6857984
#define OFF_XZ     8496384
#define OFF_XI     15049984
#define OFF_DT     18326784
#define OFF_PROJ   21603584
#define OFF_YC     21808384

// ---------------- helpers ----------------
__device__ __forceinline__ float gelu_f(float x) {
    return 0.5f * x * (1.0f + erff(x * 0.70710678118654752f));
}
__device__ __forceinline__ float softplus_f(float x) {
    return fmaxf(x, 0.0f) + log1pf(expf(-fabsf(x)));
}

// ---------------- prep kernels ----------------
__global__ void prep_feats_k(const float* __restrict__ feats, float* __restrict__ featsp) {
    int i = blockIdx.x * 256 + threadIdx.x;
    if (i < Bsz * Tfull * 80) {
        int c = i % 80;
        int t = (i / 80) % Tfull;
        int b = i / (80 * Tfull);
        featsp[(b * 1602 + t + 1) * 80 + c] = feats[i];
    }
    if (i < Bsz * 2 * 80) {   // zero pad rows t=0 and t=1601
        int c = i % 80; int r = i / 80;
        int b = r >> 1; int t = (r & 1) ? 1601 : 0;
        featsp[(b * 1602 + t) * 80 + c] = 0.0f;
    }
}

__global__ void zero_out1p_pads_k(float* __restrict__ out1p) {
    int i = blockIdx.x * 256 + threadIdx.x;   // 8192 elems
    if (i < Bsz * 2 * 512) {
        int c = i % 512; int r = i / 512;
        int b = r >> 1; int t = (r & 1) ? 801 : 0;
        out1p[(b * 802 + t) * 512 + c] = 0.0f;
    }
}

// conv1_w (512,80,3) -> w1t[(k*80+c)*512+o]
__global__ void tr_w1_k(const float* __restrict__ w, float* __restrict__ wt) {
    int i = blockIdx.x * 256 + threadIdx.x;
    if (i >= 512 * 80 * 3) return;
    int k = i % 3; int c = (i / 3) % 80; int o = i / 240;
    wt[(k * 80 + c) * 512 + o] = w[i];
}
// conv2_w (512,512,3) -> w2t[(k*512+c)*512+o]
__global__ void tr_w2_k(const float* __restrict__ w, float* __restrict__ wt) {
    int i = blockIdx.x * 256 + threadIdx.x;
    if (i >= 512 * 512 * 3) return;
    int k = i % 3; int c = (i / 3) % 512; int o = i / 1536;
    wt[(k * 512 + c) * 512 + o] = w[i];
}

// ---------------- generic fused SGEMM ----------------
// C[orow(m), n] (op)= act( A[arow(m) + k] * B[k*N + n] + bias[n] )
//   arow(m) = (m / a_rpb)*a_bs + (m % a_rpb)*a_rs
//   orow(m) = (m / o_rpb)*o_bs + (m % o_rpb)*o_rs
// act: 0 none, 1 GELU, 2 softplus.  accum: += existing C (residual).
// Requires: M % 64 == 0, N % 64 == 0, K % 16 == 0, 4-float alignment of all offsets.
__global__ void sgemm_k(const float* __restrict__ A, const float* __restrict__ B,
                        const float* __restrict__ bias, float* __restrict__ C,
                        int M, int N, int K,
                        int a_rpb, int a_bs, int a_rs,
                        int o_rpb, int o_bs, int o_rs,
                        int act, int accum) {
    __shared__ float As[16][64];   // [k][m]
    __shared__ float Bs[16][64];   // [k][n]
    int tid = threadIdx.x;              // 256 threads
    int bm = blockIdx.y * 64;
    int bn = blockIdx.x * 64;
    int tx = tid & 15, ty = tid >> 4;

    // A load mapping: row ra = tid>>2 (0..63), cols ca..ca+3
    int ra = tid >> 2;
    int ca = (tid & 3) << 2;
    int am = bm + ra;
    int aoff = (am / a_rpb) * a_bs + (am % a_rpb) * a_rs;
    // B load mapping: row rb = tid>>4 (0..15), cols cbb..cbb+3
    int rb = tid >> 4;
    int cbb = (tid & 15) << 2;

    float acc[4][4];
#pragma unroll
    for (int i = 0; i < 4; i++)
#pragma unroll
        for (int j = 0; j < 4; j++) acc[i][j] = 0.0f;

    for (int kk = 0; kk < K; kk += 16) {
        float4 av = *(const float4*)(A + aoff + kk + ca);
        As[ca + 0][ra] = av.x;
        As[ca + 1][ra] = av.y;
        As[ca + 2][ra] = av.z;
        As[ca + 3][ra] = av.w;
        float4 bv = *(const float4*)(B + (kk + rb) * N + bn + cbb);
        *(float4*)&Bs[rb][cbb] = bv;
        __syncthreads();
#pragma unroll
        for (int k = 0; k < 16; k++) {
            float a0[4], b0[4];
#pragma unroll
            for (int i = 0; i < 4; i++) a0[i] = As[k][ty * 4 + i];
#pragma unroll
            for (int j = 0; j < 4; j++) b0[j] = Bs[k][tx * 4 + j];
#pragma unroll
            for (int i = 0; i < 4; i++)
#pragma unroll
                for (int j = 0; j < 4; j++) acc[i][j] = fmaf(a0[i], b0[j], acc[i][j]);
        }
        __syncthreads();
    }

#pragma unroll
    for (int i = 0; i < 4; i++) {
        int gm = bm + ty * 4 + i;
        int ooff = (gm / o_rpb) * o_bs + (gm % o_rpb) * o_rs;
#pragma unroll
        for (int j = 0; j < 4; j++) {
            int gn = bn + tx * 4 + j;
            float v = acc[i][j];
            if (bias) v += bias[gn];
            if (act == 1) v = gelu_f(v);
            else if (act == 2) v = softplus_f(v);
            if (accum) v += C[ooff + gn];
            C[ooff + gn] = v;
        }
    }
}

// ---------------- RMSNorm ----------------
__global__ void rmsnorm_k(const float* __restrict__ x, const float* __restrict__ w,
                          float* __restrict__ xn) {
    int row = blockIdx.x;
    int tid = threadIdx.x;   // 128
    const float* xr = x + row * Dm;
    float v[4];
    float s = 0.0f;
#pragma unroll
    for (int i = 0; i < 4; i++) { v[i] = xr[tid + 128 * i]; s += v[i] * v[i]; }
#pragma unroll
    for (int o = 16; o; o >>= 1) s += __shfl_xor_sync(0xffffffffu, s, o);
    __shared__ float ws[4];
    if ((tid & 31) == 0) ws[tid >> 5] = s;
    __syncthreads();
    float tot = ws[0] + ws[1] + ws[2] + ws[3];
    float rs = rsqrtf(tot * (1.0f / Dm) + 1e-5f);
#pragma unroll
    for (int i = 0; i < 4; i++)
        xn[row * Dm + tid + 128 * i] = v[i] * rs * w[tid + 128 * i];
}

// ---------------- depthwise causal conv (K=4) + SiLU ----------------
__global__ void dwconv_k(const float* __restrict__ xz, const float* __restrict__ cw,
                         const float* __restrict__ cb, float* __restrict__ xi) {
    int idx = blockIdx.x * 256 + threadIdx.x;   // over 3200*1024
    if (idx >= M4 * DIc) return;
    int d = idx & (DIc - 1);
    int m = idx >> 10;
    int t = m % T4;
    float w0 = cw[d * 4 + 0], w1 = cw[d * 4 + 1], w2 = cw[d * 4 + 2], w3 = cw[d * 4 + 3];
    const float* base = xz + m * 2048 + d;
    float acc = w3 * base[0];
    if (t >= 1) acc = fmaf(w2, base[-2048], acc);
    if (t >= 2) acc = fmaf(w1, base[-2 * 2048], acc);
    if (t >= 3) acc = fmaf(w0, base[-3 * 2048], acc);
    acc += cb[d];
    xi[idx] = acc / (1.0f + expf(-acc));   // SiLU
}

// ---------------- selective-scan (fused dA/dBx/y/Dskip/z-gate) ----------------
// warp: lanes 0..15 -> (d, n=0..15), lanes 16..31 -> (d+1, n=0..15)
__global__ void scan_k(const float* __restrict__ dt, const float* __restrict__ xi,
                       const float* __restrict__ proj, const float* __restrict__ xz,
                       const float* __restrict__ A_log, const float* __restrict__ dskip,
                       float* __restrict__ yc) {
    int w = (blockIdx.x * blockDim.x + threadIdx.x) >> 5;   // 0..4095
    int lane = threadIdx.x & 31;
    int b = w >> 9;            // 512 d-pairs per batch
    int dp = w & 511;
    int d = dp * 2 + (lane >> 4);
    int n = lane & 15;
    float Ac = -expf(A_log[d * Nst + n]);
    float dsk = dskip[d];
    float h = 0.0f;
    int mb = b * T4;
    for (int t = 0; t < T4; t++) {
        int m = mb + t;
        float dtv = dt[m * DIc + d];
        float xiv = xi[m * DIc + d];
        float Bv = proj[m * 64 + 32 + n];
        float Cv = proj[m * 64 + 48 + n];
        float dA = __expf(dtv * Ac);
        h = fmaf(dA, h, dtv * xiv * Bv);
        float p = h * Cv;
        p += __shfl_xor_sync(0xffffffffu, p, 8);
        p += __shfl_xor_sync(0xffffffffu, p, 4);
        p += __shfl_xor_sync(0xffffffffu, p, 2);
        p += __shfl_xor_sync(0xffffffffu, p, 1);
        if (n == 0) {
            float zv = xz[m * 2048 + DIc + d];
            float yv = p + dsk * xiv;
            yc[m * DIc + d] = yv * zv / (1.0f + __expf(-zv));
        }
    }
}

// ---------------- output lengths ----------------
__global__ void lens_k(const int* __restrict__ fl, float* __restrict__ out, int out_size) {
    int b = threadIdx.x;
    if (b < Bsz && out_size >= M4 * Vv + Bsz) {
        int v = fl[b] >> 2;
        if (v < 1) v = 1;
        out[M4 * Vv + b] = (float)v;
    }
}

// ---------------- launcher ----------------
extern "C" void kernel_launch(void* const* d_in, const int* in_sizes, int n_in,
                              void* d_out, int out_size) {
    (void)in_sizes; (void)n_in;
    const float* feats    = (const float*)d_in[0];
    const int*   feat_lens= (const int*)  d_in[1];
    const float* conv1_w  = (const float*)d_in[2];
    const float* conv1_b  = (const float*)d_in[3];
    const float* conv2_w  = (const float*)d_in[4];
    const float* conv2_b  = (const float*)d_in[5];
    const float* norm_w   = (const float*)d_in[6];
    const float* in_proj  = (const float*)d_in[7];
    const float* dwc_w    = (const float*)d_in[8];
    const float* dwc_b    = (const float*)d_in[9];
    const float* x_proj   = (const float*)d_in[10];
    const float* dt_w     = (const float*)d_in[11];
    const float* dt_b     = (const float*)d_in[12];
    const float* A_log    = (const float*)d_in[13];
    const float* D_skip   = (const float*)d_in[14];
    const float* out_proj = (const float*)d_in[15];
    const float* head_w   = (const float*)d_in[16];
    const float* head_b   = (const float*)d_in[17];
    float* out = (float*)d_out;

    void* sym = nullptr;
    cudaGetSymbolAddress(&sym, g_buf);
    float* gb     = (float*)sym;
    float* featsp = gb + OFF_FEATSP;
    float* w1t    = gb + OFF_W1T;
    float* w2t    = gb + OFF_W2T;
    float* out1p  = gb + OFF_OUT1P;
    float* x      = gb + OFF_X;
    float* xn     = gb + OFF_XN;
    float* xz     = gb + OFF_XZ;
    float* xi     = gb + OFF_XI;
    float* dtbuf  = gb + OFF_DT;
    float* proj   = gb + OFF_PROJ;
    float* yc     = gb + OFF_YC;

    // prep
    prep_feats_k<<<(Bsz * Tfull * 80 + 255) / 256, 256>>>(feats, featsp);
    zero_out1p_pads_k<<<(Bsz * 2 * 512 + 255) / 256, 256>>>(out1p);
    tr_w1_k<<<(512 * 80 * 3 + 255) / 256, 256>>>(conv1_w, w1t);
    tr_w2_k<<<(512 * 512 * 3 + 255) / 256, 256>>>(conv2_w, w2t);

    // conv1 as GEMM: M=6400, K=240, N=512; A rows = padded feats slices; out -> out1p (pad-shifted)
    sgemm_k<<<dim3(512 / 64, M2 / 64), 256>>>(
        featsp, w1t, conv1_b, out1p + 512,
        M2, 512, 240,
        800, 1602 * 80, 160,
        800, 802 * 512, 512,
        /*act=*/1, /*accum=*/0);

    // conv2 as GEMM: M=3200, K=1536, N=512 -> x (contiguous)
    sgemm_k<<<dim3(512 / 64, M4 / 64), 256>>>(
        out1p, w2t, conv2_b, x,
        M4, 512, 1536,
        400, 802 * 512, 1024,
        M4, 0, 512,
        /*act=*/1, /*accum=*/0);

    // mamba blocks
    for (int l = 0; l < Ll; l++) {
        rmsnorm_k<<<M4, 128>>>(x, norm_w + l * Dm, xn);

        // xz = xn @ in_proj[l]  (3200x512 @ 512x2048)
        sgemm_k<<<dim3(2048 / 64, M4 / 64), 256>>>(
            xn, in_proj + (size_t)l * Dm * 2 * DIc, nullptr, xz,
            M4, 2048, 512,
            M4, 0, 512,
            M4, 0, 2048,
            0, 0);

        dwconv_k<<<(M4 * DIc + 255) / 256, 256>>>(
            xz, dwc_w + l * DIc * 4, dwc_b + l * DIc, xi);

        // proj = xi @ x_proj[l]  (3200x1024 @ 1024x64)
        sgemm_k<<<dim3(64 / 64, M4 / 64), 256>>>(
            xi, x_proj + (size_t)l * DIc * 64, nullptr, proj,
            M4, 64, 1024,
            M4, 0, 1024,
            M4, 0, 64,
            0, 0);

        // dt = softplus(proj[:, :32] @ dt_w[l] + dt_b[l])  (3200x32 @ 32x1024)
        sgemm_k<<<dim3(1024 / 64, M4 / 64), 256>>>(
            proj, dt_w + (size_t)l * Rr * DIc, dt_b + l * DIc, dtbuf,
            M4, 1024, 32,
            M4, 0, 64,
            M4, 0, 1024,
            /*act=*/2, 0);

        // fused selective scan + Dskip + z-gate -> yc
        scan_k<<<512, 256>>>(dtbuf, xi, proj, xz,
                             A_log + (size_t)l * DIc * Nst, D_skip + l * DIc, yc);

        // x += yc @ out_proj[l]  (3200x1024 @ 1024x512, residual accumulate)
        sgemm_k<<<dim3(512 / 64, M4 / 64), 256>>>(
            yc, out_proj + (size_t)l * DIc * Dm, nullptr, x,
            M4, 512, 1024,
            M4, 0, 1024,
            M4, 0, 512,
            0, /*accum=*/1);
    }

    // logits = x @ head_w + head_b  (3200x512 @ 512x1024) -> d_out
    sgemm_k<<<dim3(1024 / 64, M4 / 64), 256>>>(
        x, head_w, head_b, out,
        M4, 1024, 512,
        M4, 0, 512,
        M4, 0, 1024,
        0, 0);

    lens_k<<<1, 32>>>(feat_lens, out, out_size);
}

// round 2
// speedup vs baseline: 1.1407x; 1.1407x over previous
#include <cuda_runtime.h>
#include <math.h>
#include <stdint.h>

// ---------------- problem constants ----------------
#define Bsz   8
#define Tfull 1600
#define Dm    512
#define DIc   1024
#define Nst   16
#define Rr    32
#define Ll    8
#define Vv    1024
#define T4    400
#define M4    (Bsz*T4)    // 3200 rows after subsampling
#define M2    (Bsz*800)   // 6400 rows after conv1

// ---------------- scratch buffer (single __device__ array) ----------------
__device__ float g_buf[25085184];

#define OFF_FEATSP 0
#define OFF_W1T    1025280
#define OFF_W2T    1148160
#define OFF_OUT1P  1934592
#define OFF_X      5219584
#define OFF_XN     6857984
#define OFF_XZ     8496384
#define OFF_XI     15049984
#define OFF_DT     18326784
#define OFF_PROJ   21603584
#define OFF_YC     21808384

// ---------------- helpers ----------------
__device__ __forceinline__ float gelu_f(float x) {
    return 0.5f * x * (1.0f + erff(x * 0.70710678118654752f));
}
__device__ __forceinline__ float softplus_f(float x) {
    return fmaxf(x, 0.0f) + log1pf(expf(-fabsf(x)));
}
__device__ __forceinline__ void split_tf32(float v, uint32_t& hi, uint32_t& lo) {
    uint32_t u = __float_as_uint(v) & 0xffffe000u;
    hi = u;
    lo = __float_as_uint(v - __uint_as_float(u));
}
__device__ __forceinline__ void mma8(float* c, const uint32_t* a, const uint32_t* b) {
    asm volatile(
        "mma.sync.aligned.m16n8k8.row.col.f32.tf32.tf32.f32 "
        "{%0,%1,%2,%3},{%4,%5,%6,%7},{%8,%9},{%0,%1,%2,%3};"
        : "+f"(c[0]), "+f"(c[1]), "+f"(c[2]), "+f"(c[3])
        : "r"(a[0]), "r"(a[1]), "r"(a[2]), "r"(a[3]), "r"(b[0]), "r"(b[1]));
}

// ---------------- prep kernels ----------------
__global__ void prep_feats_k(const float* __restrict__ feats, float* __restrict__ featsp) {
    int i = blockIdx.x * 256 + threadIdx.x;
    if (i < Bsz * Tfull * 80) {
        int c = i % 80;
        int t = (i / 80) % Tfull;
        int b = i / (80 * Tfull);
        featsp[(b * 1602 + t + 1) * 80 + c] = feats[i];
    }
    if (i < Bsz * 2 * 80) {
        int c = i % 80; int r = i / 80;
        int b = r >> 1; int t = (r & 1) ? 1601 : 0;
        featsp[(b * 1602 + t) * 80 + c] = 0.0f;
    }
}

__global__ void zero_out1p_pads_k(float* __restrict__ out1p) {
    int i = blockIdx.x * 256 + threadIdx.x;
    if (i < Bsz * 2 * 512) {
        int c = i % 512; int r = i / 512;
        int b = r >> 1; int t = (r & 1) ? 801 : 0;
        out1p[(b * 802 + t) * 512 + c] = 0.0f;
    }
}

__global__ void tr_w1_k(const float* __restrict__ w, float* __restrict__ wt) {
    int i = blockIdx.x * 256 + threadIdx.x;
    if (i >= 512 * 80 * 3) return;
    int k = i % 3; int c = (i / 3) % 80; int o = i / 240;
    wt[(k * 80 + c) * 512 + o] = w[i];
}
__global__ void tr_w2_k(const float* __restrict__ w, float* __restrict__ wt) {
    int i = blockIdx.x * 256 + threadIdx.x;
    if (i >= 512 * 512 * 3) return;
    int k = i % 3; int c = (i / 3) % 512; int o = i / 1536;
    wt[(k * 512 + c) * 512 + o] = w[i];
}

// ---------------- tensor-core GEMM (3xTF32 split, fp32-accurate) ----------------
// C[orow(m), n] (op)= act( A[arow(m) + k] * B[k*N + n] + bias[n] )
//   arow(m) = (m / a_rpb)*a_bs + (m % a_rpb)*a_rs
//   orow(m) = (m / o_rpb)*o_bs + (m % o_rpb)*o_rs
// act: 0 none, 1 GELU, 2 softplus.  accum: += existing C.
// Requires: M % 128 == 0, N % BN == 0, K % 16 == 0, float4 alignment.
template<int BN>
__global__ void __launch_bounds__(256, 1) tgemm_k(
        const float* __restrict__ A, const float* __restrict__ B,
        const float* __restrict__ bias, float* __restrict__ C,
        int M, int N, int K,
        int a_rpb, int a_bs, int a_rs,
        int o_rpb, int o_bs, int o_rs,
        int act, int accum) {
    constexpr int BM = 128, BK = 16;
    constexpr int MW = (BN == 128) ? 2 : 4;
    constexpr int NW = 8 / MW;
    constexpr int MT = BM / (MW * 16);     // 4 (BN=128) or 2 (BN=64)
    constexpr int NT = BN / (NW * 8);      // 4
    __shared__ float As[2][BK][BM + 8];
    __shared__ float Bs[2][BK][BN + 8];

    int tid = threadIdx.x;
    int wid = tid >> 5, lane = tid & 31;
    int g = lane >> 2, ctg = lane & 3;
    int wm = wid % MW, wn = wid / MW;
    int bm = blockIdx.y * BM, bn = blockIdx.x * BN;

    // global load indices
    int am_ld = tid & 127;                    // A row within tile
    int ak_ld = (tid >> 7) * 8;               // A k base (0 or 8)
    int gmA = bm + am_ld;
    long aoff = (long)(gmA / a_rpb) * a_bs + (long)(gmA % a_rpb) * a_rs;
    int bk_ld = tid >> 4;                     // 0..15
    int bn_ld = (tid & 15) * (BN / 16);       // *8 or *4

    float acc[MT][NT][4];
#pragma unroll
    for (int i = 0; i < MT; i++)
#pragma unroll
        for (int j = 0; j < NT; j++)
#pragma unroll
            for (int r = 0; r < 4; r++) acc[i][j][r] = 0.0f;

    float4 ag0, ag1, bg0, bg1;
    auto loadG = [&](int kk) {
        const float* ap = A + aoff + kk + ak_ld;
        ag0 = *(const float4*)ap;
        ag1 = *(const float4*)(ap + 4);
        const float* bp = B + (long)(kk + bk_ld) * N + bn + bn_ld;
        bg0 = *(const float4*)bp;
        if (BN == 128) bg1 = *(const float4*)(bp + 4);
    };
    auto storeS = [&](int s) {
        As[s][ak_ld + 0][am_ld] = ag0.x;
        As[s][ak_ld + 1][am_ld] = ag0.y;
        As[s][ak_ld + 2][am_ld] = ag0.z;
        As[s][ak_ld + 3][am_ld] = ag0.w;
        As[s][ak_ld + 4][am_ld] = ag1.x;
        As[s][ak_ld + 5][am_ld] = ag1.y;
        As[s][ak_ld + 6][am_ld] = ag1.z;
        As[s][ak_ld + 7][am_ld] = ag1.w;
        *(float4*)&Bs[s][bk_ld][bn_ld] = bg0;
        if (BN == 128) *(float4*)&Bs[s][bk_ld][bn_ld + 4] = bg1;
    };

    int nchunk = K >> 4;
    loadG(0);
    storeS(0);
    __syncthreads();

    for (int c = 0; c < nchunk; ++c) {
        int s = c & 1;
        if (c + 1 < nchunk) loadG((c + 1) << 4);

        // compute on buffer s
#pragma unroll
        for (int ks = 0; ks < 16; ks += 8) {
            uint32_t ahi[MT][4], alo[MT][4], bhi[NT][2], blo[NT][2];
#pragma unroll
            for (int i = 0; i < MT; i++) {
                int m0 = wm * MT * 16 + i * 16;
                split_tf32(As[s][ks + ctg][m0 + g],         ahi[i][0], alo[i][0]);
                split_tf32(As[s][ks + ctg][m0 + g + 8],     ahi[i][1], alo[i][1]);
                split_tf32(As[s][ks + ctg + 4][m0 + g],     ahi[i][2], alo[i][2]);
                split_tf32(As[s][ks + ctg + 4][m0 + g + 8], ahi[i][3], alo[i][3]);
            }
#pragma unroll
            for (int j = 0; j < NT; j++) {
                int n0 = wn * NT * 8 + j * 8;
                split_tf32(Bs[s][ks + ctg][n0 + g],     bhi[j][0], blo[j][0]);
                split_tf32(Bs[s][ks + ctg + 4][n0 + g], bhi[j][1], blo[j][1]);
            }
#pragma unroll
            for (int i = 0; i < MT; i++)
#pragma unroll
                for (int j = 0; j < NT; j++) {
                    mma8(acc[i][j], ahi[i], bhi[j]);
                    mma8(acc[i][j], ahi[i], blo[j]);
                    mma8(acc[i][j], alo[i], bhi[j]);
                }
        }

        if (c + 1 < nchunk) {
            storeS(s ^ 1);
            __syncthreads();
        }
    }

    // epilogue
#pragma unroll
    for (int i = 0; i < MT; i++) {
#pragma unroll
        for (int r = 0; r < 2; r++) {
            int gm = bm + wm * MT * 16 + i * 16 + g + r * 8;
            long ooff = (long)(gm / o_rpb) * o_bs + (long)(gm % o_rpb) * o_rs;
#pragma unroll
            for (int j = 0; j < NT; j++) {
                int gn = bn + wn * NT * 8 + j * 8 + 2 * ctg;
#pragma unroll
                for (int h = 0; h < 2; h++) {
                    float v = acc[i][j][r * 2 + h];
                    if (bias) v += bias[gn + h];
                    if (act == 1) v = gelu_f(v);
                    else if (act == 2) v = softplus_f(v);
                    if (accum) v += C[ooff + gn + h];
                    C[ooff + gn + h] = v;
                }
            }
        }
    }
}

// ---------------- RMSNorm ----------------
__global__ void rmsnorm_k(const float* __restrict__ x, const float* __restrict__ w,
                          float* __restrict__ xn) {
    int row = blockIdx.x;
    int tid = threadIdx.x;   // 128
    const float* xr = x + row * Dm;
    float v[4];
    float s = 0.0f;
#pragma unroll
    for (int i = 0; i < 4; i++) { v[i] = xr[tid + 128 * i]; s += v[i] * v[i]; }
#pragma unroll
    for (int o = 16; o; o >>= 1) s += __shfl_xor_sync(0xffffffffu, s, o);
    __shared__ float ws[4];
    if ((tid & 31) == 0) ws[tid >> 5] = s;
    __syncthreads();
    float tot = ws[0] + ws[1] + ws[2] + ws[3];
    float rs = rsqrtf(tot * (1.0f / Dm) + 1e-5f);
#pragma unroll
    for (int i = 0; i < 4; i++)
        xn[row * Dm + tid + 128 * i] = v[i] * rs * w[tid + 128 * i];
}

// ---------------- depthwise causal conv (K=4) + SiLU ----------------
__global__ void dwconv_k(const float* __restrict__ xz, const float* __restrict__ cw,
                         const float* __restrict__ cb, float* __restrict__ xi) {
    int idx = blockIdx.x * 256 + threadIdx.x;
    if (idx >= M4 * DIc) return;
    int d = idx & (DIc - 1);
    int m = idx >> 10;
    int t = m % T4;
    float w0 = cw[d * 4 + 0], w1 = cw[d * 4 + 1], w2 = cw[d * 4 + 2], w3 = cw[d * 4 + 3];
    const float* base = xz + m * 2048 + d;
    float acc = w3 * base[0];
    if (t >= 1) acc = fmaf(w2, base[-2048], acc);
    if (t >= 2) acc = fmaf(w1, base[-2 * 2048], acc);
    if (t >= 3) acc = fmaf(w0, base[-3 * 2048], acc);
    acc += cb[d];
    xi[idx] = acc / (1.0f + expf(-acc));   // SiLU
}

// ---------------- selective-scan (fused dA/dBx/y/Dskip/z-gate) ----------------
__global__ void scan_k(const float* __restrict__ dt, const float* __restrict__ xi,
                       const float* __restrict__ proj, const float* __restrict__ xz,
                       const float* __restrict__ A_log, const float* __restrict__ dskip,
                       float* __restrict__ yc) {
    int w = (blockIdx.x * blockDim.x + threadIdx.x) >> 5;   // 0..4095
    int lane = threadIdx.x & 31;
    int b = w >> 9;
    int dp = w & 511;
    int d = dp * 2 + (lane >> 4);
    int n = lane & 15;
    float Ac = -expf(A_log[d * Nst + n]);
    float dsk = dskip[d];
    float h = 0.0f;
    int mb = b * T4;
    for (int t = 0; t < T4; t++) {
        int m = mb + t;
        float dtv = dt[m * DIc + d];
        float xiv = xi[m * DIc + d];
        float Bv = proj[m * 64 + 32 + n];
        float Cv = proj[m * 64 + 48 + n];
        float dA = __expf(dtv * Ac);
        h = fmaf(dA, h, dtv * xiv * Bv);
        float p = h * Cv;
        p += __shfl_xor_sync(0xffffffffu, p, 8);
        p += __shfl_xor_sync(0xffffffffu, p, 4);
        p += __shfl_xor_sync(0xffffffffu, p, 2);
        p += __shfl_xor_sync(0xffffffffu, p, 1);
        if (n == 0) {
            float zv = xz[m * 2048 + DIc + d];
            float yv = p + dsk * xiv;
            yc[m * DIc + d] = yv * zv / (1.0f + __expf(-zv));
        }
    }
}

// ---------------- output lengths ----------------
__global__ void lens_k(const int* __restrict__ fl, float* __restrict__ out, int out_size) {
    int b = threadIdx.x;
    if (b < Bsz && out_size >= M4 * Vv + Bsz) {
        int v = fl[b] >> 2;
        if (v < 1) v = 1;
        out[M4 * Vv + b] = (float)v;
    }
}

// ---------------- launcher ----------------
extern "C" void kernel_launch(void* const* d_in, const int* in_sizes, int n_in,
                              void* d_out, int out_size) {
    (void)in_sizes; (void)n_in;
    const float* feats    = (const float*)d_in[0];
    const int*   feat_lens= (const int*)  d_in[1];
    const float* conv1_w  = (const float*)d_in[2];
    const float* conv1_b  = (const float*)d_in[3];
    const float* conv2_w  = (const float*)d_in[4];
    const float* conv2_b  = (const float*)d_in[5];
    const float* norm_w   = (const float*)d_in[6];
    const float* in_proj  = (const float*)d_in[7];
    const float* dwc_w    = (const float*)d_in[8];
    const float* dwc_b    = (const float*)d_in[9];
    const float* x_proj   = (const float*)d_in[10];
    const float* dt_w     = (const float*)d_in[11];
    const float* dt_b     = (const float*)d_in[12];
    const float* A_log    = (const float*)d_in[13];
    const float* D_skip   = (const float*)d_in[14];
    const float* out_proj = (const float*)d_in[15];
    const float* head_w   = (const float*)d_in[16];
    const float* head_b   = (const float*)d_in[17];
    float* out = (float*)d_out;

    void* sym = nullptr;
    cudaGetSymbolAddress(&sym, g_buf);
    float* gb     = (float*)sym;
    float* featsp = gb + OFF_FEATSP;
    float* w1t    = gb + OFF_W1T;
    float* w2t    = gb + OFF_W2T;
    float* out1p  = gb + OFF_OUT1P;
    float* x      = gb + OFF_X;
    float* xn     = gb + OFF_XN;
    float* xz     = gb + OFF_XZ;
    float* xi     = gb + OFF_XI;
    float* dtbuf  = gb + OFF_DT;
    float* proj   = gb + OFF_PROJ;
    float* yc     = gb + OFF_YC;

    // prep
    prep_feats_k<<<(Bsz * Tfull * 80 + 255) / 256, 256>>>(feats, featsp);
    zero_out1p_pads_k<<<(Bsz * 2 * 512 + 255) / 256, 256>>>(out1p);
    tr_w1_k<<<(512 * 80 * 3 + 255) / 256, 256>>>(conv1_w, w1t);
    tr_w2_k<<<(512 * 512 * 3 + 255) / 256, 256>>>(conv2_w, w2t);

    // conv1 as GEMM: M=6400, K=240, N=512 (im2col over padded feats), GELU
    tgemm_k<128><<<dim3(512 / 128, M2 / 128), 256>>>(
        featsp, w1t, conv1_b, out1p + 512,
        M2, 512, 240,
        800, 1602 * 80, 160,
        800, 802 * 512, 512,
        /*act=*/1, /*accum=*/0);

    // conv2 as GEMM: M=3200, K=1536, N=512 -> x, GELU
    tgemm_k<128><<<dim3(512 / 128, M4 / 128), 256>>>(
        out1p, w2t, conv2_b, x,
        M4, 512, 1536,
        400, 802 * 512, 1024,
        M4, 0, 512,
        /*act=*/1, /*accum=*/0);

    // mamba blocks
    for (int l = 0; l < Ll; l++) {
        rmsnorm_k<<<M4, 128>>>(x, norm_w + l * Dm, xn);

        // xz = xn @ in_proj[l]  (3200x512 @ 512x2048)
        tgemm_k<128><<<dim3(2048 / 128, M4 / 128), 256>>>(
            xn, in_proj + (size_t)l * Dm * 2 * DIc, nullptr, xz,
            M4, 2048, 512,
            M4, 0, 512,
            M4, 0, 2048,
            0, 0);

        dwconv_k<<<(M4 * DIc + 255) / 256, 256>>>(
            xz, dwc_w + l * DIc * 4, dwc_b + l * DIc, xi);

        // proj = xi @ x_proj[l]  (3200x1024 @ 1024x64)
        tgemm_k<64><<<dim3(64 / 64, M4 / 128), 256>>>(
            xi, x_proj + (size_t)l * DIc * 64, nullptr, proj,
            M4, 64, 1024,
            M4, 0, 1024,
            M4, 0, 64,
            0, 0);

        // dt = softplus(proj[:, :32] @ dt_w[l] + dt_b[l])  (3200x32 @ 32x1024)
        tgemm_k<128><<<dim3(1024 / 128, M4 / 128), 256>>>(
            proj, dt_w + (size_t)l * Rr * DIc, dt_b + l * DIc, dtbuf,
            M4, 1024, 32,
            M4, 0, 64,
            M4, 0, 1024,
            /*act=*/2, 0);

        // fused selective scan + Dskip + z-gate -> yc
        scan_k<<<512, 256>>>(dtbuf, xi, proj, xz,
                             A_log + (size_t)l * DIc * Nst, D_skip + l * DIc, yc);

        // x += yc @ out_proj[l]  (3200x1024 @ 1024x512, residual accumulate)
        tgemm_k<128><<<dim3(512 / 128, M4 / 128), 256>>>(
            yc, out_proj + (size_t)l * DIc * Dm, nullptr, x,
            M4, 512, 1024,
            M4, 0, 1024,
            M4, 0, 512,
            0, /*accum=*/1);
    }

    // logits = x @ head_w + head_b  (3200x512 @ 512x1024) -> d_out
    tgemm_k<128><<<dim3(1024 / 128, M4 / 128), 256>>>(
        x, head_w, head_b, out,
        M4, 1024, 512,
        M4, 0, 512,
        M4, 0, 1024,
        0, 0);

    lens_k<<<1, 32>>>(feat_lens, out, out_size);
}